// round 4
// baseline (speedup 1.0000x reference)
#include <cuda_runtime.h>
#include <cuda_bf16.h>
#include <cstdint>

// LSTMModel: B=4096, T=512, D=8, H=64, 2 layers + FC(64->1)
//
// R4 design (sm_103a):
//  - 128 blocks x 256 threads, 32 batch/block, all weights in smem (~225 KB).
//  - Thread (j = tid>>2, g = tid&3): 4 gate rows of hidden unit j for the
//    8 batch elements of group g. Warp = 8 j x 4 g -> 1-wavefront smem loads.
//  - f32x2 lanes pack (k, k+1): both FFMA2 operands load directly from smem
//    as 8B pairs -> no lane-duplication MOVs. Horizontal add in epilogue.
//  - Weights stored [k2][gate][j][2] (k-pair interleaved); h stored
//    [k2][g*20 + b*2 + par] (group stride 20 floats -> conflict-free + 16B
//    aligned vector loads).
//  - 3 barriers/step: A(z0) | C(cell0, stage x) | E(z1) | F(cell1).
//  - Activations via ex2.approx + rcp.approx (rel_err ~6e-7 headroom kept).

#define ULL unsigned long long

static __device__ __forceinline__ float2 upk(ULL v) {
    float2 f; asm("mov.b64 {%0, %1}, %2;" : "=f"(f.x), "=f"(f.y) : "l"(v)); return f;
}
static __device__ __forceinline__ ULL ffma2(ULL a, ULL b, ULL c) {
    ULL d; asm("fma.rn.f32x2 %0, %1, %2, %3;" : "=l"(d) : "l"(a), "l"(b), "l"(c)); return d;
}
static __device__ __forceinline__ float ex2f(float x) {
    float r; asm("ex2.approx.f32 %0, %1;" : "=f"(r) : "f"(x)); return r;
}
static __device__ __forceinline__ float rcpf(float x) {
    float r; asm("rcp.approx.f32 %0, %1;" : "=f"(r) : "f"(x)); return r;
}
static __device__ __forceinline__ float sigm(float x) {
    return rcpf(1.0f + ex2f(-1.4426950408889634f * x));
}
static __device__ __forceinline__ float tanh_fast(float x) {
    float ax = fabsf(x);
    float p = ex2f(-2.8853900817779268f * ax);
    float r = (1.0f - p) * rcpf(1.0f + p);
    return copysignf(r, x);
}
static __device__ __forceinline__ float hadd(ULL a) {
    float2 f = upk(a); return f.x + f.y;
}

static constexpr int B = 4096;
static constexpr int T = 512;
static constexpr int D = 8;
static constexpr int NBATCH_BLK = 32;

// h/x layout constants: row = k-pair, 4 groups * 20 floats (16 used + 4 pad)
static constexpr int GSTR = 20;   // group stride (floats) — bank-phase shifted
static constexpr int HROW = 80;   // row stride (floats), 320B (16B aligned)

// smem float offsets
static constexpr int OFF_WIH0 = 0;                      //  4*512 = 2048
static constexpr int OFF_WHH0 = OFF_WIH0 + 2048;        // 32*512 = 16384
static constexpr int OFF_WIH1 = OFF_WHH0 + 16384;
static constexpr int OFF_WHH1 = OFF_WIH1 + 16384;
static constexpr int OFF_B0   = OFF_WHH1 + 16384;       // 256  [j*4+q]
static constexpr int OFF_B1   = OFF_B0 + 256;           // 256
static constexpr int OFF_WFC  = OFF_B1 + 256;           // 64
static constexpr int OFF_H0   = OFF_WFC + 64;           // 32*80 = 2560
static constexpr int OFF_H1   = OFF_H0 + 32 * HROW;     // 2560
static constexpr int OFF_XS   = OFF_H1 + 32 * HROW;     // 2 * 4*80 = 640
static constexpr int SMEM_FLOATS = OFF_XS + 640;
static constexpr int SMEM_BYTES = SMEM_FLOATS * 4;      // 230,144 B

// One k-pair: 4 gate-weight pairs (LDS.64 each) x 8 batch h-pairs (4x LDS.128)
// -> 32 FFMA2, zero packing MOVs.
static __device__ __forceinline__ void k2step(ULL (&a)[4][8],
                                              const float* __restrict__ wb,
                                              const float* __restrict__ hb) {
    ULL w[4];
    #pragma unroll
    for (int q = 0; q < 4; ++q) w[q] = *(const ULL*)(wb + q * 128);
    ULL h[8];
    #pragma unroll
    for (int p = 0; p < 4; ++p) {
        ulonglong2 u = *(const ulonglong2*)(hb + p * 4);
        h[2 * p] = u.x; h[2 * p + 1] = u.y;
    }
    #pragma unroll
    for (int q = 0; q < 4; ++q)
        #pragma unroll
        for (int b = 0; b < 8; ++b)
            a[q][b] = ffma2(w[q], h[b], a[q][b]);
}

static __device__ __forceinline__ void zero_acc(ULL (&a)[4][8]) {
    #pragma unroll
    for (int q = 0; q < 4; ++q)
        #pragma unroll
        for (int b = 0; b < 8; ++b) a[q][b] = 0ULL;
}

// LSTM cell for 8 batch elements; hdst points at this thread's (j, g) slot,
// stride 2 floats per batch element (k-pair interleaved layout).
static __device__ __forceinline__ void cell_layer(ULL (&a)[4][8], float4 bz,
                                                  float (&c)[8], float* hdst) {
    #pragma unroll
    for (int b = 0; b < 8; ++b) {
        float zi = hadd(a[0][b]) + bz.x;
        float zf = hadd(a[1][b]) + bz.y;
        float zg = hadd(a[2][b]) + bz.z;
        float zo = hadd(a[3][b]) + bz.w;
        float i  = sigm(zi);
        float f  = sigm(zf);
        float gg = tanh_fast(zg);
        float o  = sigm(zo);
        float cn = f * c[b] + i * gg;
        c[b] = cn;
        hdst[2 * b] = o * tanh_fast(cn);
    }
}

extern __shared__ float sm[];

__global__ void __launch_bounds__(256, 1)
lstm_kernel(const float* __restrict__ x,
            const float* __restrict__ Wih0, const float* __restrict__ Whh0,
            const float* __restrict__ bih0, const float* __restrict__ bhh0,
            const float* __restrict__ Wih1, const float* __restrict__ Whh1,
            const float* __restrict__ bih1, const float* __restrict__ bhh1,
            const float* __restrict__ Wfc,  const float* __restrict__ bfc,
            float* __restrict__ out)
{
    const int tid = threadIdx.x;
    const int j = tid >> 2;        // hidden unit 0..63
    const int g = tid & 3;         // batch group 0..3 (8 batch each)
    const int Bb = blockIdx.x * NBATCH_BLK;

    // ---- load + transform weights: sm[k2*512 + q*128 + j*2 + par] = W[q*64+j][k2*2+par]
    for (int idx = tid; idx < 16384; idx += 256) {
        int par = idx & 1;
        int jj  = (idx >> 1) & 63;
        int q   = (idx >> 7) & 3;
        int k2  = idx >> 9;
        int row = q * 64 + jj;
        int col = k2 * 2 + par;
        sm[OFF_WHH0 + idx] = Whh0[row * 64 + col];
        sm[OFF_WIH1 + idx] = Wih1[row * 64 + col];
        sm[OFF_WHH1 + idx] = Whh1[row * 64 + col];
    }
    for (int idx = tid; idx < 2048; idx += 256) {
        int par = idx & 1;
        int jj  = (idx >> 1) & 63;
        int q   = (idx >> 7) & 3;
        int d2  = idx >> 9;
        sm[OFF_WIH0 + idx] = Wih0[(q * 64 + jj) * 8 + d2 * 2 + par];
    }
    {   // combined biases, layout [j][q] -> index tid
        int q = tid & 3, jj = tid >> 2;
        sm[OFF_B0 + tid] = bih0[q * 64 + jj] + bhh0[q * 64 + jj];
        sm[OFF_B1 + tid] = bih1[q * 64 + jj] + bhh1[q * 64 + jj];
    }
    if (tid < 64) sm[OFF_WFC + tid] = Wfc[tid];
    for (int idx = tid; idx < 2 * 32 * HROW; idx += 256)
        sm[OFF_H0 + idx] = 0.0f;   // zero h0 and h1 (contiguous)

    // x prefetch mapping: thread loads x[Bb + bl][t][dl]
    const int bl = tid >> 3;       // 0..31
    const int dl = tid & 7;        // 0..7
    const float* xptr = x + (size_t)(Bb + bl) * (T * D) + dl;
    const int xoff = (dl >> 1) * HROW + (bl >> 3) * GSTR + (bl & 7) * 2 + (dl & 1);
    float x0 = __ldg(xptr);
    sm[OFF_XS + xoff] = x0;        // buffer 0, t=0

    __syncthreads();

    // per-thread constant pointers
    const int jw = j * 2;
    const float* h0g = sm + OFF_H0 + g * GSTR;
    const float* h1g = sm + OFF_H1 + g * GSTR;
    float* h0dst = sm + OFF_H0 + (j >> 1) * HROW + g * GSTR + (j & 1);
    float* h1dst = sm + OFF_H1 + (j >> 1) * HROW + g * GSTR + (j & 1);
    const float4 b0v = *(const float4*)(sm + OFF_B0 + j * 4);
    const float4 b1v = *(const float4*)(sm + OFF_B1 + j * 4);

    float c0[8], c1[8];
    #pragma unroll
    for (int b = 0; b < 8; ++b) { c0[b] = 0.0f; c1[b] = 0.0f; }

    ULL acc[4][8];

    for (int t = 0; t < T; ++t) {
        float xn = 0.0f;
        if (t + 1 < T) xn = __ldg(xptr + (t + 1) * D);
        const float* xb = sm + OFF_XS + (t & 1) * 320 + g * GSTR;

        // ---------- phase A: z0 = x@Wih0^T + h0_prev@Whh0^T ----------
        zero_acc(acc);
        #pragma unroll
        for (int d2 = 0; d2 < 4; ++d2)
            k2step(acc, sm + OFF_WIH0 + d2 * 512 + jw, xb + d2 * HROW);
        #pragma unroll 4
        for (int k2 = 0; k2 < 32; ++k2)
            k2step(acc, sm + OFF_WHH0 + k2 * 512 + jw, h0g + k2 * HROW);

        __syncthreads();   // all reads of h0(old) + xs(cur) done

        // ---------- phase C: layer-0 cell update, stage next x ----------
        cell_layer(acc, b0v, c0, h0dst);
        sm[OFF_XS + ((t + 1) & 1) * 320 + xoff] = xn;

        __syncthreads();   // h0(new) + xs(next) visible

        // ---------- phase E: z1 = h0_new@Wih1^T + h1_prev@Whh1^T ----------
        zero_acc(acc);
        #pragma unroll 4
        for (int k2 = 0; k2 < 32; ++k2)
            k2step(acc, sm + OFF_WIH1 + k2 * 512 + jw, h0g + k2 * HROW);
        #pragma unroll 4
        for (int k2 = 0; k2 < 32; ++k2)
            k2step(acc, sm + OFF_WHH1 + k2 * 512 + jw, h1g + k2 * HROW);

        __syncthreads();   // all reads of h1(old) done

        // ---------- phase F: layer-1 cell update (overlaps next A) ----------
        cell_layer(acc, b1v, c1, h1dst);
        // no trailing barrier: next-step A reads only h0/xs (fenced above);
        // h1(new) is next read in E(t+1), fenced by that step's two barriers.
    }

    __syncthreads();       // final h1 visible

    // ---------- FC head: out[b] = h1[b] . Wfc + bfc ----------
    if (tid < NBATCH_BLK) {
        float acc2 = __ldg(bfc);
        #pragma unroll 8
        for (int k = 0; k < 64; ++k)
            acc2 += sm[OFF_H1 + (k >> 1) * HROW + (tid >> 3) * GSTR + (tid & 7) * 2 + (k & 1)]
                  * sm[OFF_WFC + k];
        out[Bb + tid] = acc2;
    }
}

extern "C" void kernel_launch(void* const* d_in, const int* in_sizes, int n_in,
                              void* d_out, int out_size) {
    (void)in_sizes; (void)n_in; (void)out_size;
    const float* x    = (const float*)d_in[0];
    const float* Wih0 = (const float*)d_in[1];
    const float* Whh0 = (const float*)d_in[2];
    const float* bih0 = (const float*)d_in[3];
    const float* bhh0 = (const float*)d_in[4];
    const float* Wih1 = (const float*)d_in[5];
    const float* Whh1 = (const float*)d_in[6];
    const float* bih1 = (const float*)d_in[7];
    const float* bhh1 = (const float*)d_in[8];
    const float* Wfc  = (const float*)d_in[9];
    const float* bfc  = (const float*)d_in[10];
    float* out = (float*)d_out;

    cudaFuncSetAttribute(lstm_kernel,
                         cudaFuncAttributeMaxDynamicSharedMemorySize, SMEM_BYTES);
    lstm_kernel<<<B / NBATCH_BLK, 256, SMEM_BYTES>>>(
        x, Wih0, Whh0, bih0, bhh0, Wih1, Whh1, bih1, bhh1, Wfc, bfc, out);
}

// round 8
// speedup vs baseline: 1.2812x; 1.2812x over previous
#include <cuda_runtime.h>
#include <cuda_bf16.h>
#include <cstdint>

// LSTMModel: B=4096, T=512, D=8, H=64, 2 layers + FC(64->1)
//
// R5 = R3 layout (best known) + phase restructure to hide MUFU under FFMA:
//  - 128 blocks x 256 threads, 32 batch/block, all weights in smem (~222 KB).
//  - Thread (j = tid&63, g = tid>>6): 4 gate rows of unit j for 8 batch
//    (4 f32x2 batch-pairs). fma.rn.f32x2 inner product.
//  - Phases per step (3 barriers, was 4):
//      A: z0 = Wih0@x + Whh0@h0_old
//      bar1
//      C: z1 += Whh1@h1_old  INTERLEAVED with cell0 (MUFU hidden), stage x
//      bar2
//      E: z1 += Wih1@h0_new
//      bar3
//      F: cell1 -> h1   (no barrier: overlaps next step's A)

#define ULL unsigned long long

static __device__ __forceinline__ ULL pk2(float v) {
    ULL r; asm("mov.b64 %0, {%1, %1};" : "=l"(r) : "f"(v)); return r;
}
static __device__ __forceinline__ ULL pkf2(float a, float b) {
    ULL r; asm("mov.b64 %0, {%1, %2};" : "=l"(r) : "f"(a), "f"(b)); return r;
}
static __device__ __forceinline__ float2 upk(ULL v) {
    float2 f; asm("mov.b64 {%0, %1}, %2;" : "=f"(f.x), "=f"(f.y) : "l"(v)); return f;
}
static __device__ __forceinline__ ULL ffma2(ULL a, ULL b, ULL c) {
    ULL d; asm("fma.rn.f32x2 %0, %1, %2, %3;" : "=l"(d) : "l"(a), "l"(b), "l"(c)); return d;
}
static __device__ __forceinline__ float ex2f(float x) {
    float r; asm("ex2.approx.f32 %0, %1;" : "=f"(r) : "f"(x)); return r;
}
static __device__ __forceinline__ float rcpf(float x) {
    float r; asm("rcp.approx.f32 %0, %1;" : "=f"(r) : "f"(x)); return r;
}
static __device__ __forceinline__ float sigm(float x) {
    return rcpf(1.0f + ex2f(-1.4426950408889634f * x));
}
static __device__ __forceinline__ float tanh_fast(float x) {
    float ax = fabsf(x);
    float p = ex2f(-2.8853900817779268f * ax);
    float r = (1.0f - p) * rcpf(1.0f + p);
    return copysignf(r, x);
}

static constexpr int B = 4096;
static constexpr int T = 512;
static constexpr int D = 8;
static constexpr int NBATCH_BLK = 32;
static constexpr int HSTRIDE = 36;      // padded row stride (floats) for h state

// smem float offsets (identical to R3)
static constexpr int OFF_WIH0 = 0;                    //  8*256
static constexpr int OFF_WHH0 = OFF_WIH0 + 2048;      // 64*256
static constexpr int OFF_WIH1 = OFF_WHH0 + 16384;     // 64*256
static constexpr int OFF_WHH1 = OFF_WIH1 + 16384;     // 64*256
static constexpr int OFF_B0   = OFF_WHH1 + 16384;     // 256
static constexpr int OFF_B1   = OFF_B0 + 256;         // 256
static constexpr int OFF_WFC  = OFF_B1 + 256;         // 64
static constexpr int OFF_H0   = OFF_WFC + 64;         // 64*36
static constexpr int OFF_H1   = OFF_H0 + 64 * HSTRIDE;// 64*36
static constexpr int OFF_XS   = OFF_H1 + 64 * HSTRIDE;// 2*256
static constexpr int SMEM_FLOATS = OFF_XS + 512;
static constexpr int SMEM_BYTES = SMEM_FLOATS * 4;    // 227,584 B

// Accumulate 4 gates x 4 batch-pairs from one k-slice into a[q*4+p].
// wb: &W[k][j*4] (LDS.128)   hb: 4 pairs (2x LDS.128 broadcast)
static __device__ __forceinline__ void acc_step(ULL (&a)[16],
                                                const float* __restrict__ wb,
                                                const float* __restrict__ hb) {
    float4 w = *(const float4*)(wb);
    ulonglong2 hA = *(const ulonglong2*)(hb);
    ulonglong2 hB = *(const ulonglong2*)(hb + 4);
    ULL h0 = hA.x, h1 = hA.y, h2 = hB.x, h3 = hB.y;
    ULL w0 = pk2(w.x), w1 = pk2(w.y), w2 = pk2(w.z), w3 = pk2(w.w);
    a[0]  = ffma2(w0, h0, a[0]);  a[1]  = ffma2(w0, h1, a[1]);
    a[2]  = ffma2(w0, h2, a[2]);  a[3]  = ffma2(w0, h3, a[3]);
    a[4]  = ffma2(w1, h0, a[4]);  a[5]  = ffma2(w1, h1, a[5]);
    a[6]  = ffma2(w1, h2, a[6]);  a[7]  = ffma2(w1, h3, a[7]);
    a[8]  = ffma2(w2, h0, a[8]);  a[9]  = ffma2(w2, h1, a[9]);
    a[10] = ffma2(w2, h2, a[10]); a[11] = ffma2(w2, h3, a[11]);
    a[12] = ffma2(w3, h0, a[12]); a[13] = ffma2(w3, h1, a[13]);
    a[14] = ffma2(w3, h2, a[14]); a[15] = ffma2(w3, h3, a[15]);
}

static __device__ __forceinline__ void init_acc(ULL (&a)[16], float4 bz) {
    ULL bi = pk2(bz.x), bf = pk2(bz.y), bg = pk2(bz.z), bo = pk2(bz.w);
    a[0] = a[1] = a[2] = a[3] = bi;
    a[4] = a[5] = a[6] = a[7] = bf;
    a[8] = a[9] = a[10] = a[11] = bg;
    a[12] = a[13] = a[14] = a[15] = bo;
}

// LSTM cell for one batch-pair p. Returns packed h, updates packed c.
static __device__ __forceinline__ ULL cell_pair(const ULL (&a)[16], int p, ULL& c) {
    float2 i2 = upk(a[p]), f2 = upk(a[4 + p]), g2 = upk(a[8 + p]), o2 = upk(a[12 + p]);
    float2 c2 = upk(c);
    float i0 = sigm(i2.x), f0 = sigm(f2.x), g0 = tanh_fast(g2.x), o0 = sigm(o2.x);
    float i1 = sigm(i2.y), f1 = sigm(f2.y), g1 = tanh_fast(g2.y), o1 = sigm(o2.y);
    float cn0 = f0 * c2.x + i0 * g0;
    float cn1 = f1 * c2.y + i1 * g1;
    c = pkf2(cn0, cn1);
    return pkf2(o0 * tanh_fast(cn0), o1 * tanh_fast(cn1));
}

extern __shared__ float sm[];

__global__ void __launch_bounds__(256, 1)
lstm_kernel(const float* __restrict__ x,
            const float* __restrict__ Wih0, const float* __restrict__ Whh0,
            const float* __restrict__ bih0, const float* __restrict__ bhh0,
            const float* __restrict__ Wih1, const float* __restrict__ Whh1,
            const float* __restrict__ bih1, const float* __restrict__ bhh1,
            const float* __restrict__ Wfc,  const float* __restrict__ bfc,
            float* __restrict__ out)
{
    const int tid = threadIdx.x;
    const int j = tid & 63;        // hidden unit
    const int g = tid >> 6;        // group (0..3): batch 8g..8g+7
    const int Bb = blockIdx.x * NBATCH_BLK;

    // ---- load + transpose weights into smem (R3 layout) ----
    for (int idx = tid; idx < 2048; idx += 256) {
        int d = idx >> 8, r = idx & 255, jj = r >> 2, q = r & 3;
        sm[OFF_WIH0 + idx] = Wih0[(q * 64 + jj) * 8 + d];
    }
    for (int idx = tid; idx < 16384; idx += 256) {
        int k = idx >> 8, r = idx & 255, jj = r >> 2, q = r & 3;
        int row = (q * 64 + jj) * 64 + k;
        sm[OFF_WHH0 + idx] = Whh0[row];
        sm[OFF_WIH1 + idx] = Wih1[row];
        sm[OFF_WHH1 + idx] = Whh1[row];
    }
    {
        int jj = tid >> 2, q = tid & 3;
        sm[OFF_B0 + tid] = bih0[q * 64 + jj] + bhh0[q * 64 + jj];
        sm[OFF_B1 + tid] = bih1[q * 64 + jj] + bhh1[q * 64 + jj];
    }
    if (tid < 64) sm[OFF_WFC + tid] = Wfc[tid];
    for (int idx = tid; idx < 2 * 64 * HSTRIDE; idx += 256)
        sm[OFF_H0 + idx] = 0.0f;   // zero h0 and h1 (contiguous)

    // x prefetch mapping: thread loads x[Bb + bl][t][dl]
    const int bl = tid >> 3;       // 0..31
    const int dl = tid & 7;        // 0..7
    const float* xptr = x + (size_t)(Bb + bl) * (T * D) + dl;
    float x0 = __ldg(xptr);        // t = 0
    __syncthreads();
    sm[OFF_XS + dl * 32 + bl] = x0;

    ULL c0[4] = {0, 0, 0, 0};      // packed cell state, layer 0 (4 pairs)
    ULL c1[4] = {0, 0, 0, 0};      // layer 1

    const int hoff = g * 8;        // float offset of this group's 4 pairs
    float* h0dst = sm + OFF_H0 + j * HSTRIDE + hoff;
    float* h1dst = sm + OFF_H1 + j * HSTRIDE + hoff;
    const float4 b0v = *(const float4*)(sm + OFF_B0 + j * 4);
    const float4 b1v = *(const float4*)(sm + OFF_B1 + j * 4);
    const int jw = j * 4;

    __syncthreads();   // weights + x stage for t=0 visible

    ULL a0[16], a1[16];

    for (int t = 0; t < T; ++t) {
        const int cur = (t & 1) * 256;
        const int nxt = 256 - cur;
        float xn = 0.0f;
        if (t + 1 < T) xn = __ldg(xptr + (t + 1) * D);

        // ---------- phase A: z0 = x@Wih0^T + h0_old@Whh0^T ----------
        init_acc(a0, b0v);
        #pragma unroll
        for (int d = 0; d < D; ++d)
            acc_step(a0, sm + OFF_WIH0 + d * 256 + jw, sm + OFF_XS + cur + d * 32 + hoff);
        #pragma unroll 8
        for (int k = 0; k < 64; ++k)
            acc_step(a0, sm + OFF_WHH0 + k * 256 + jw, sm + OFF_H0 + k * HSTRIDE + hoff);

        __syncthreads();   // bar1: reads of h0_old + xs(cur) done; F(t-1) h1 writes fenced

        // ---------- phase C: z1 += Whh1@h1_old, interleaved with cell0 ----------
        // MUFU latency of cell0 hides under the 1024 independent FFMA2.
        init_acc(a1, b1v);
        #pragma unroll
        for (int p = 0; p < 4; ++p) {
            #pragma unroll
            for (int k = p * 16; k < p * 16 + 16; ++k)
                acc_step(a1, sm + OFF_WHH1 + k * 256 + jw, sm + OFF_H1 + k * HSTRIDE + hoff);
            ULL hp = cell_pair(a0, p, c0[p]);
            *(ULL*)(h0dst + 2 * p) = hp;
        }
        sm[OFF_XS + nxt + dl * 32 + bl] = xn;   // stage next x

        __syncthreads();   // bar2: h0_new + xs(next) visible; h1_old reads done

        // ---------- phase E: z1 += Wih1@h0_new ----------
        #pragma unroll 8
        for (int k = 0; k < 64; ++k)
            acc_step(a1, sm + OFF_WIH1 + k * 256 + jw, sm + OFF_H0 + k * HSTRIDE + hoff);

        __syncthreads();   // bar3: reads of h1_old... (all z1 inputs consumed)

        // ---------- phase F: cell1 -> h1 (overlaps next step's phase A) ----------
        #pragma unroll
        for (int p = 0; p < 4; ++p) {
            ULL hp = cell_pair(a1, p, c1[p]);
            *(ULL*)(h1dst + 2 * p) = hp;
        }
        // no trailing barrier: next A reads only h0/xs (disjoint); C(t+1)'s
        // h1 reads are fenced by bar1(t+1).
    }

    __syncthreads();       // final h1 visible

    // ---------- FC head: out[b] = h1[b] . Wfc + bfc ----------
    if (tid < NBATCH_BLK) {
        float acc2 = __ldg(bfc);
        #pragma unroll 8
        for (int k = 0; k < 64; ++k)
            acc2 += sm[OFF_H1 + k * HSTRIDE + tid] * sm[OFF_WFC + k];
        out[Bb + tid] = acc2;
    }
}

extern "C" void kernel_launch(void* const* d_in, const int* in_sizes, int n_in,
                              void* d_out, int out_size) {
    (void)in_sizes; (void)n_in; (void)out_size;
    const float* x    = (const float*)d_in[0];
    const float* Wih0 = (const float*)d_in[1];
    const float* Whh0 = (const float*)d_in[2];
    const float* bih0 = (const float*)d_in[3];
    const float* bhh0 = (const float*)d_in[4];
    const float* Wih1 = (const float*)d_in[5];
    const float* Whh1 = (const float*)d_in[6];
    const float* bih1 = (const float*)d_in[7];
    const float* bhh1 = (const float*)d_in[8];
    const float* Wfc  = (const float*)d_in[9];
    const float* bfc  = (const float*)d_in[10];
    float* out = (float*)d_out;

    cudaFuncSetAttribute(lstm_kernel,
                         cudaFuncAttributeMaxDynamicSharedMemorySize, SMEM_BYTES);
    lstm_kernel<<<B / NBATCH_BLK, 256, SMEM_BYTES>>>(
        x, Wih0, Whh0, bih0, bhh0, Wih1, Whh1, bih1, bhh1, Wfc, bfc, out);
}